// round 14
// baseline (speedup 1.0000x reference)
#include <cuda_runtime.h>
#include <cuda_fp16.h>
#include <math.h>
#include <stdint.h>

#define B_  2
#define L_  2048
#define D_  2048
#define HD_ 64
#define NH_ 32
#define DC_ 2048
#define EPS 1.1920929e-7f

// ---------------- scratch (device globals; no allocation) ----------------
__device__ float  g_ss [B_ * 2 * D_];                  // [b][4096] shift|scale
__device__ __half g_qkvh[(size_t)B_ * L_ * 3 * D_];    // qkv rows=(b,l), fp16
__device__ __half g_hh [(size_t)B_ * L_ * D_];         // modulated hidden (fp16)
__device__ __half g_wqh[(size_t)3 * D_ * D_];          // w_qkv fp16
__device__ __half g_woh[(size_t)D_ * D_];              // w_out fp16
__device__ __half g_qh [(size_t)B_ * NH_ * L_ * HD_];  // q (pre-scaled), fp16
__device__ __half g_kh [(size_t)B_ * NH_ * L_ * HD_];
__device__ __half g_vh [(size_t)B_ * NH_ * L_ * HD_];
__device__ __half g_oh [(size_t)B_ * L_ * D_];         // attn out fp16

// ---------------- helpers ------------------------------------------------
__device__ __forceinline__ uint32_t pack_h2(float lo, float hi) {
    uint32_t u;
    asm("cvt.rn.f16x2.f32 %0, %1, %2;" : "=r"(u) : "f"(hi), "f"(lo));
    return u;
}
__device__ __forceinline__ float2 unpack_h2(uint32_t u) {
    __half2 h = *reinterpret_cast<__half2*>(&u);
    return __half22float2(h);
}
__device__ __forceinline__ void mma_f16(float* c, const uint32_t* a,
                                        const uint32_t* b) {
    asm volatile(
        "mma.sync.aligned.m16n8k16.row.col.f32.f16.f16.f32 "
        "{%0,%1,%2,%3}, {%4,%5,%6,%7}, {%8,%9}, {%0,%1,%2,%3};"
        : "+f"(c[0]), "+f"(c[1]), "+f"(c[2]), "+f"(c[3])
        : "r"(a[0]), "r"(a[1]), "r"(a[2]), "r"(a[3]), "r"(b[0]), "r"(b[1]));
}
#define LDSM_X4(r0, r1, r2, r3, addr)                                         \
    asm volatile("ldmatrix.sync.aligned.m8n8.x4.shared.b16 {%0,%1,%2,%3}, [%4];" \
        : "=r"(r0), "=r"(r1), "=r"(r2), "=r"(r3) : "r"(addr))
#define LDSM_X4_T(r0, r1, r2, r3, addr)                                       \
    asm volatile("ldmatrix.sync.aligned.m8n8.x4.trans.shared.b16 {%0,%1,%2,%3}, [%4];" \
        : "=r"(r0), "=r"(r1), "=r"(r2), "=r"(r3) : "r"(addr))

// ---------------- one-shot weight conversion to fp16 ---------------------
__global__ void cvtw_h(__half* __restrict__ dst, const float* __restrict__ src) {
    int i = (blockIdx.x * 256 + threadIdx.x) * 4;
    float4 v = *reinterpret_cast<const float4*>(src + i);
    uint2 u = make_uint2(pack_h2(v.x, v.y), pack_h2(v.z, v.w));
    *reinterpret_cast<uint2*>(dst + i) = u;
}

// ======= fp16 ldmatrix GEMM NT: C[M,N] = A[M,K]*B[N,K]^T =================
// BM=BN=128, BK=32, register double-buffer (LDG->regs->STS, attention-style),
// 2 stages (32KB static), 256 threads, warp tile 64x32, 2 CTAs/SM.
template <bool HALF_OUT>
__global__ void __launch_bounds__(256, 2)
gemm_h(void* __restrict__ Cv, const __half* __restrict__ A,
       const __half* __restrict__ B, int M, int N, int K) {
    __shared__ uint32_t As[2][128][16];
    __shared__ uint32_t Bs[2][128][16];

    int tid = threadIdx.x;
    int m0 = blockIdx.y * 128, n0 = blockIdx.x * 128;
    int wid = tid >> 5, lane = tid & 31;
    int wm = (wid & 1) * 64, wn = (wid >> 1) * 32;
    int qr = lane >> 2, qc = lane & 3;
    int i8 = lane & 7, g = lane >> 3;

    int cr = tid >> 2, cc = tid & 3;
    int cw  = 4 * (cc ^ ((cr >> 1) & 3));
    int cw2 = 4 * (cc ^ (((cr + 64) >> 1) & 3));
    const __half* Asrc0 = A + (size_t)(m0 + cr) * K + cc * 8;
    const __half* Asrc1 = A + (size_t)(m0 + cr + 64) * K + cc * 8;
    const __half* Bsrc0 = B + (size_t)(n0 + cr) * K + cc * 8;
    const __half* Bsrc1 = B + (size_t)(n0 + cr + 64) * K + cc * 8;

    uint32_t sA = (uint32_t)__cvta_generic_to_shared(&As[0][0][0]);
    uint32_t sB = (uint32_t)__cvta_generic_to_shared(&Bs[0][0][0]);

    uint4 pa0, pa1, pb0, pb1;

    // prologue: ktile 0 -> buf0, prefetch ktile 1 into regs
    pa0 = *reinterpret_cast<const uint4*>(Asrc0);
    pa1 = *reinterpret_cast<const uint4*>(Asrc1);
    pb0 = *reinterpret_cast<const uint4*>(Bsrc0);
    pb1 = *reinterpret_cast<const uint4*>(Bsrc1);
    *reinterpret_cast<uint4*>(&As[0][cr][cw])      = pa0;
    *reinterpret_cast<uint4*>(&As[0][cr + 64][cw2]) = pa1;
    *reinterpret_cast<uint4*>(&Bs[0][cr][cw])      = pb0;
    *reinterpret_cast<uint4*>(&Bs[0][cr + 64][cw2]) = pb1;
    pa0 = *reinterpret_cast<const uint4*>(Asrc0 + 32);
    pa1 = *reinterpret_cast<const uint4*>(Asrc1 + 32);
    pb0 = *reinterpret_cast<const uint4*>(Bsrc0 + 32);
    pb1 = *reinterpret_cast<const uint4*>(Bsrc1 + 32);
    __syncthreads();

    int arow = wm + i8 + (g & 1) * 8;
    int acg  = g >> 1;
    int brow = wn + i8 + (g >> 1) * 8;
    int bcg  = g & 1;

    float acc[4][4][4] = {};
    int NT = K >> 5;
    for (int kt = 0; kt < NT; kt++) {
        int p = kt & 1;
        // 1) store regs (ktile kt+1) into buf p^1 (its readers synced at kt-1)
        if (kt + 1 < NT) {
            *reinterpret_cast<uint4*>(&As[p ^ 1][cr][cw])       = pa0;
            *reinterpret_cast<uint4*>(&As[p ^ 1][cr + 64][cw2]) = pa1;
            *reinterpret_cast<uint4*>(&Bs[p ^ 1][cr][cw])       = pb0;
            *reinterpret_cast<uint4*>(&Bs[p ^ 1][cr + 64][cw2]) = pb1;
        }
        // 2) prefetch ktile kt+2 into regs
        if (kt + 2 < NT) {
            int kh = (kt + 2) * 32;
            pa0 = *reinterpret_cast<const uint4*>(Asrc0 + kh);
            pa1 = *reinterpret_cast<const uint4*>(Asrc1 + kh);
            pb0 = *reinterpret_cast<const uint4*>(Bsrc0 + kh);
            pb1 = *reinterpret_cast<const uint4*>(Bsrc1 + kh);
        }
        // 3) compute on buf p
        uint32_t stoff = p * 8192;
#pragma unroll
        for (int kc = 0; kc < 2; kc++) {
            uint32_t af[4][4], bf[4][2];
#pragma unroll
            for (int mt = 0; mt < 4; mt++) {
                int r = arow + mt * 16;
                int w = r * 16 + 4 * ((2 * kc + acg) ^ ((r >> 1) & 3));
                LDSM_X4(af[mt][0], af[mt][1], af[mt][2], af[mt][3],
                        sA + stoff + w * 4);
            }
#pragma unroll
            for (int nt2 = 0; nt2 < 2; nt2++) {
                int r = brow + nt2 * 16;
                int w = r * 16 + 4 * ((2 * kc + bcg) ^ ((r >> 1) & 3));
                LDSM_X4(bf[nt2 * 2][0], bf[nt2 * 2][1],
                        bf[nt2 * 2 + 1][0], bf[nt2 * 2 + 1][1],
                        sB + stoff + w * 4);
            }
#pragma unroll
            for (int mt = 0; mt < 4; mt++)
#pragma unroll
                for (int nt = 0; nt < 4; nt++)
                    mma_f16(acc[mt][nt], af[mt], bf[nt]);
        }
        __syncthreads();
    }

#pragma unroll
    for (int mt = 0; mt < 4; mt++) {
        int row = m0 + wm + mt * 16 + qr;
#pragma unroll
        for (int nt = 0; nt < 4; nt++) {
            int col = n0 + wn + nt * 8 + qc * 2;
            if (HALF_OUT) {
                __half* C = (__half*)Cv;
                *reinterpret_cast<uint32_t*>(C + (size_t)row * N + col) =
                    pack_h2(acc[mt][nt][0], acc[mt][nt][1]);
                *reinterpret_cast<uint32_t*>(C + (size_t)(row + 8) * N + col) =
                    pack_h2(acc[mt][nt][2], acc[mt][nt][3]);
            } else {
                float* C = (float*)Cv;
                *reinterpret_cast<float2*>(C + (size_t)row * N + col) =
                    make_float2(acc[mt][nt][0], acc[mt][nt][1]);
                *reinterpret_cast<float2*>(C + (size_t)(row + 8) * N + col) =
                    make_float2(acc[mt][nt][2], acc[mt][nt][3]);
            }
        }
    }
}

// ---------------- 1) ss = condition @ w_ada^T  (warp per output) ---------
__global__ void ada_kernel(const float* __restrict__ cond,
                           const float* __restrict__ w_ada) {
    int w    = (blockIdx.x * blockDim.x + threadIdx.x) >> 5;
    int lane = threadIdx.x & 31;
    int b = w >> 12;
    int j = w & 4095;
    const float4* c4 = reinterpret_cast<const float4*>(cond + (size_t)b * DC_);
    const float4* w4 = reinterpret_cast<const float4*>(w_ada + (size_t)j * DC_);
    float s = 0.f;
#pragma unroll
    for (int q = 0; q < 16; q++) {
        float4 a  = c4[lane + q * 32];
        float4 bb = w4[lane + q * 32];
        s += a.x * bb.x + a.y * bb.y + a.z * bb.z + a.w * bb.w;
    }
#pragma unroll
    for (int o = 16; o; o >>= 1) s += __shfl_xor_sync(0xffffffffu, s, o);
    if (lane == 0) g_ss[b * 4096 + j] = s;
}

// ------- 2) h = fp16(rmsnorm(x)*(1+scale)+shift) -------------------------
__global__ void rmsada_kernel(const float* __restrict__ x) {
    int row = blockIdx.x;
    int b   = row >> 11;
    int t   = threadIdx.x;
    const float4* xr = reinterpret_cast<const float4*>(x + (size_t)row * D_);
    float4 v0 = xr[t], v1 = xr[t + 256];
    float s = v0.x*v0.x + v0.y*v0.y + v0.z*v0.z + v0.w*v0.w
            + v1.x*v1.x + v1.y*v1.y + v1.z*v1.z + v1.w*v1.w;
    __shared__ float red[256];
    red[t] = s; __syncthreads();
    for (int o = 128; o; o >>= 1) { if (t < o) red[t] += red[t + o]; __syncthreads(); }
    float inv = rsqrtf(red[0] * (1.0f / D_) + EPS);
    const float* shift = g_ss + b * 4096;
    const float* scale = shift + D_;
    uint2* hr = reinterpret_cast<uint2*>(g_hh + (size_t)row * D_);
    {
        int d = t * 4;
        float4 sc = *reinterpret_cast<const float4*>(scale + d);
        float4 sh = *reinterpret_cast<const float4*>(shift + d);
        hr[t] = make_uint2(
            pack_h2(v0.x * inv * (1.f + sc.x) + sh.x,
                    v0.y * inv * (1.f + sc.y) + sh.y),
            pack_h2(v0.z * inv * (1.f + sc.z) + sh.z,
                    v0.w * inv * (1.f + sc.w) + sh.w));
    }
    {
        int d = (t + 256) * 4;
        float4 sc = *reinterpret_cast<const float4*>(scale + d);
        float4 sh = *reinterpret_cast<const float4*>(shift + d);
        hr[t + 256] = make_uint2(
            pack_h2(v1.x * inv * (1.f + sc.x) + sh.x,
                    v1.y * inv * (1.f + sc.y) + sh.y),
            pack_h2(v1.z * inv * (1.f + sc.z) + sh.z,
                    v1.w * inv * (1.f + sc.w) + sh.w));
    }
}

// ------- 4) per-head rmsnorm + qk_w + RoPE -> fp16 q/k/v -----------------
__global__ void qkrope_kernel(const float* __restrict__ rope,
                              const float* __restrict__ qkw) {
    int row = blockIdx.x;                // b*L + l
    int b   = row >> 11;
    int l   = row & 2047;
    int t   = threadIdx.x;
    int h   = t >> 3;
    int sub = t & 7;
    int d0  = sub * 8;

    const __half* src = g_qkvh + (size_t)row * (3 * D_) + h * HD_ + d0;
    uint4 qu = *reinterpret_cast<const uint4*>(src);
    uint4 ku = *reinterpret_cast<const uint4*>(src + D_);
    uint4 vu = *reinterpret_cast<const uint4*>(src + 2 * D_);

    float2 qf[4], kf[4];
    qf[0] = unpack_h2(qu.x); qf[1] = unpack_h2(qu.y);
    qf[2] = unpack_h2(qu.z); qf[3] = unpack_h2(qu.w);
    kf[0] = unpack_h2(ku.x); kf[1] = unpack_h2(ku.y);
    kf[2] = unpack_h2(ku.z); kf[3] = unpack_h2(ku.w);

    float sq = 0.f, sk = 0.f;
#pragma unroll
    for (int i = 0; i < 4; i++) {
        sq += qf[i].x * qf[i].x + qf[i].y * qf[i].y;
        sk += kf[i].x * kf[i].x + kf[i].y * kf[i].y;
    }
#pragma unroll
    for (int o = 4; o; o >>= 1) {
        sq += __shfl_xor_sync(0xffffffffu, sq, o);
        sk += __shfl_xor_sync(0xffffffffu, sk, o);
    }
    float qi = rsqrtf(sq * (1.0f / HD_) + EPS);
    float ki = rsqrtf(sk * (1.0f / HD_) + EPS);

    const float4* w4 = reinterpret_cast<const float4*>(qkw + d0);
    float4 w0 = w4[0], w1 = w4[1];
    const float* rbase = rope + (size_t)l * HD_ + d0;
    float4 r00 = *reinterpret_cast<const float4*>(rbase);
    float4 r01 = *reinterpret_cast<const float4*>(rbase + 4);
    float4 r10 = *reinterpret_cast<const float4*>(rbase + (size_t)L_ * HD_);
    float4 r11 = *reinterpret_cast<const float4*>(rbase + (size_t)L_ * HD_ + 4);

    float w[8]  = {w0.x, w0.y, w0.z, w0.w, w1.x, w1.y, w1.z, w1.w};
    float r0[8] = {r00.x, r00.y, r00.z, r00.w, r01.x, r01.y, r01.z, r01.w};
    float r1[8] = {r10.x, r10.y, r10.z, r10.w, r11.x, r11.y, r11.z, r11.w};

    uint32_t qo[4], ko[4];
#pragma unroll
    for (int i = 0; i < 4; i++) {
        float q0 = qf[i].x * qi * w[2 * i];
        float q1 = qf[i].y * qi * w[2 * i + 1];
        float k0 = kf[i].x * ki * w[2 * i];
        float k1 = kf[i].y * ki * w[2 * i + 1];
        float qx = q0 * r0[2 * i]     - q1 * r1[2 * i];
        float qy = q1 * r0[2 * i + 1] + q0 * r1[2 * i + 1];
        float kx = k0 * r0[2 * i]     - k1 * r1[2 * i];
        float ky = k1 * r0[2 * i + 1] + k0 * r1[2 * i + 1];
        qo[i] = pack_h2(qx * 0.125f, qy * 0.125f);
        ko[i] = pack_h2(kx, ky);
    }

    size_t orow = ((size_t)(b * NH_ + h) * L_ + l) * HD_ + d0;
    *reinterpret_cast<uint4*>(g_qh + orow) = make_uint4(qo[0], qo[1], qo[2], qo[3]);
    *reinterpret_cast<uint4*>(g_kh + orow) = make_uint4(ko[0], ko[1], ko[2], ko[3]);
    *reinterpret_cast<uint4*>(g_vh + orow) = vu;
}

// ============ 5) fp16 flash attention: BQ=128, register P ================
__global__ void __launch_bounds__(256, 2) attn_h() {
    __shared__ uint32_t Qs[128][32];
    __shared__ uint32_t Ks[2][32][32];
    __shared__ uint32_t Vs[2][32][32];

    int tid  = threadIdx.x;
    int wid  = tid >> 5, lane = tid & 31;
    int qr   = lane >> 2, qc = lane & 3;
    int i8   = lane & 7, g = lane >> 3;
    int bh   = blockIdx.y;
    int bq0  = blockIdx.x * 128;
    int qrow = wid * 16;

    const __half* Qg = g_qh + (size_t)bh * L_ * HD_;
    const __half* Kg = g_kh + (size_t)bh * L_ * HD_;
    const __half* Vg = g_vh + (size_t)bh * L_ * HD_;

    int pr = tid >> 3, pch = tid & 7;
    int pw = (pch * 4) ^ ((pr & 7) << 2);
    uint4 kp = *reinterpret_cast<const uint4*>(Kg + (size_t)pr * HD_ + pch * 8);
    uint4 vp = *reinterpret_cast<const uint4*>(Vg + (size_t)pr * HD_ + pch * 8);

#pragma unroll
    for (int t = 0; t < 4; t++) {
        int idx = tid + t * 256;
        int r = idx >> 3, ch = idx & 7;
        uint4 u = *reinterpret_cast<const uint4*>(Qg + (size_t)(bq0 + r) * HD_ + ch * 8);
        *reinterpret_cast<uint4*>(&Qs[r][(ch * 4) ^ ((r & 7) << 2)]) = u;
    }
    __syncthreads();

    uint32_t aq[4][4];
    uint32_t qbase = (uint32_t)__cvta_generic_to_shared(&Qs[0][0]);
    {
        int r = qrow + i8 + (g & 1) * 8;
#pragma unroll
        for (int kk = 0; kk < 4; kk++) {
            int ch = 2 * kk + (g >> 1);
            int w = r * 32 + ((ch * 4) ^ ((r & 7) << 2));
            LDSM_X4(aq[kk][0], aq[kk][1], aq[kk][2], aq[kk][3], qbase + w * 4);
        }
    }

    {
        *reinterpret_cast<uint4*>(&Ks[0][pr][pw]) = kp;
        *reinterpret_cast<uint4*>(&Vs[0][pr][pw]) = vp;
    }
    __syncthreads();

    uint32_t kbase = (uint32_t)__cvta_generic_to_shared(&Ks[0][0][0]);
    uint32_t vbase = (uint32_t)__cvta_generic_to_shared(&Vs[0][0][0]);
    int krow = i8 + (g >> 1) * 8;
    int vrow = i8 + (g & 1) * 8;
    int vcg  = g >> 1;

    float o[8][4] = {};
    float m_lo = -INFINITY, m_hi = -INFINITY, l_lo = 0.f, l_hi = 0.f;
    int p = 0;

    for (int c = 0; c < 64; c++) {
        if (c < 63) {
            size_t koff = (size_t)(c + 1) * 32;
            kp = *reinterpret_cast<const uint4*>(Kg + (koff + pr) * HD_ + pch * 8);
            vp = *reinterpret_cast<const uint4*>(Vg + (koff + pr) * HD_ + pch * 8);
        }

        float s[4][4] = {};
        uint32_t pbase = kbase + p * 4096;
#pragma unroll
        for (int kk = 0; kk < 4; kk++) {
            uint32_t b0[4], b1[4];
            {
                int r = krow;
                int ch = 2 * kk + (g & 1);
                int w = r * 32 + ((ch * 4) ^ ((r & 7) << 2));
                LDSM_X4(b0[0], b0[1], b0[2], b0[3], pbase + w * 4);
            }
            {
                int r = krow + 16;
                int ch = 2 * kk + (g & 1);
                int w = r * 32 + ((ch * 4) ^ ((r & 7) << 2));
                LDSM_X4(b1[0], b1[1], b1[2], b1[3], pbase + w * 4);
            }
            mma_f16(s[0], aq[kk], b0);
            mma_f16(s[1], aq[kk], b0 + 2);
            mma_f16(s[2], aq[kk], b1);
            mma_f16(s[3], aq[kk], b1 + 2);
        }

        float mx_lo = -INFINITY, mx_hi = -INFINITY;
#pragma unroll
        for (int j = 0; j < 4; j++) {
            mx_lo = fmaxf(mx_lo, fmaxf(s[j][0], s[j][1]));
            mx_hi = fmaxf(mx_hi, fmaxf(s[j][2], s[j][3]));
        }
        mx_lo = fmaxf(mx_lo, __shfl_xor_sync(0xffffffffu, mx_lo, 1));
        mx_lo = fmaxf(mx_lo, __shfl_xor_sync(0xffffffffu, mx_lo, 2));
        mx_hi = fmaxf(mx_hi, __shfl_xor_sync(0xffffffffu, mx_hi, 1));
        mx_hi = fmaxf(mx_hi, __shfl_xor_sync(0xffffffffu, mx_hi, 2));

        float mn_lo = fmaxf(m_lo, mx_lo);
        float mn_hi = fmaxf(m_hi, mx_hi);
        float cf_lo = __expf(m_lo - mn_lo);
        float cf_hi = __expf(m_hi - mn_hi);
        m_lo = mn_lo; m_hi = mn_hi;

        uint32_t ap[2][4];
        float ls_lo = 0.f, ls_hi = 0.f;
#pragma unroll
        for (int kk2 = 0; kk2 < 2; kk2++) {
#pragma unroll
            for (int jj = 0; jj < 2; jj++) {
                int j = 2 * kk2 + jj;
                uint32_t plo = pack_h2(__expf(s[j][0] - mn_lo),
                                       __expf(s[j][1] - mn_lo));
                uint32_t phi = pack_h2(__expf(s[j][2] - mn_hi),
                                       __expf(s[j][3] - mn_hi));
                ap[kk2][2 * jj]     = plo;
                ap[kk2][2 * jj + 1] = phi;
                float2 flo = unpack_h2(plo), fhi = unpack_h2(phi);
                ls_lo += flo.x + flo.y;
                ls_hi += fhi.x + fhi.y;
            }
        }
        ls_lo += __shfl_xor_sync(0xffffffffu, ls_lo, 1);
        ls_lo += __shfl_xor_sync(0xffffffffu, ls_lo, 2);
        ls_hi += __shfl_xor_sync(0xffffffffu, ls_hi, 1);
        ls_hi += __shfl_xor_sync(0xffffffffu, ls_hi, 2);
        l_lo = l_lo * cf_lo + ls_lo;
        l_hi = l_hi * cf_hi + ls_hi;

#pragma unroll
        for (int n = 0; n < 8; n++) {
            o[n][0] *= cf_lo; o[n][1] *= cf_lo;
            o[n][2] *= cf_hi; o[n][3] *= cf_hi;
        }

        uint32_t vpb = vbase + p * 4096;
#pragma unroll
        for (int kk2 = 0; kk2 < 2; kk2++) {
            int r = kk2 * 16 + vrow;
#pragma unroll
            for (int np = 0; np < 4; np++) {
                int ch = 2 * np + vcg;
                int w = r * 32 + ((ch * 4) ^ ((r & 7) << 2));
                uint32_t bv0[2], bv1[2];
                LDSM_X4_T(bv0[0], bv0[1], bv1[0], bv1[1], vpb + w * 4);
                mma_f16(o[2 * np],     ap[kk2], bv0);
                mma_f16(o[2 * np + 1], ap[kk2], bv1);
            }
        }

        if (c < 63) {
            int np2 = p ^ 1;
            *reinterpret_cast<uint4*>(&Ks[np2][pr][pw]) = kp;
            *reinterpret_cast<uint4*>(&Vs[np2][pr][pw]) = vp;
            __syncthreads();
            p = np2;
        }
    }

    int b = bh >> 5, h = bh & 31;
    float inv_lo = 1.f / l_lo, inv_hi = 1.f / l_hi;
    __half* base_lo = g_oh + (size_t)(b * L_ + bq0 + qrow + qr) * D_ + h * HD_;
    __half* base_hi = g_oh + (size_t)(b * L_ + bq0 + qrow + qr + 8) * D_ + h * HD_;
#pragma unroll
    for (int n = 0; n < 8; n++) {
        *reinterpret_cast<uint32_t*>(base_lo + 8 * n + 2 * qc) =
            pack_h2(o[n][0] * inv_lo, o[n][1] * inv_lo);
        *reinterpret_cast<uint32_t*>(base_hi + 8 * n + 2 * qc) =
            pack_h2(o[n][2] * inv_hi, o[n][3] * inv_hi);
    }
}

// -------------------------------------------------------------------------
extern "C" void kernel_launch(void* const* d_in, const int* in_sizes, int n_in,
                              void* d_out, int out_size) {
    const float* x     = (const float*)d_in[0];
    const float* cond  = (const float*)d_in[1];
    const float* rope  = (const float*)d_in[2];
    const float* w_ada = (const float*)d_in[3];
    const float* w_qkv = (const float*)d_in[4];
    const float* w_out = (const float*)d_in[5];
    const float* qk_w  = (const float*)d_in[6];
    float* out = (float*)d_out;

    void* p;
    cudaGetSymbolAddress(&p, g_qkvh); __half* pqkv = (__half*)p;
    cudaGetSymbolAddress(&p, g_hh);   __half* phh  = (__half*)p;
    cudaGetSymbolAddress(&p, g_wqh);  __half* pwq  = (__half*)p;
    cudaGetSymbolAddress(&p, g_woh);  __half* pwo  = (__half*)p;
    cudaGetSymbolAddress(&p, g_oh);   __half* poh  = (__half*)p;

    cvtw_h<<<3 * D_ * D_ / 1024, 256>>>(pwq, w_qkv);
    cvtw_h<<<D_ * D_ / 1024, 256>>>(pwo, w_out);
    ada_kernel<<<1024, 256>>>(cond, w_ada);
    rmsada_kernel<<<B_ * L_, 256>>>(x);
    gemm_h<true><<<dim3(3 * D_ / 128, B_ * L_ / 128), 256>>>(
        pqkv, phh, pwq, B_ * L_, 3 * D_, D_);
    qkrope_kernel<<<B_ * L_, 256>>>(rope, qk_w);
    attn_h<<<dim3(L_ / 128, B_ * NH_), 256>>>();
    gemm_h<false><<<dim3(D_ / 128, B_ * L_ / 128), 256>>>(
        out, poh, pwo, B_ * L_, D_, D_);
}

// round 15
// speedup vs baseline: 1.7379x; 1.7379x over previous
#include <cuda_runtime.h>
#include <cuda_fp16.h>
#include <math.h>
#include <stdint.h>

#define B_  2
#define L_  2048
#define D_  2048
#define HD_ 64
#define NH_ 32
#define DC_ 2048
#define EPS 1.1920929e-7f

// ---------------- scratch (device globals; no allocation) ----------------
__device__ float  g_ss [B_ * 2 * D_];                  // [b][4096] shift|scale
__device__ __half g_qkvh[(size_t)B_ * L_ * 3 * D_];    // qkv rows=(b,l), fp16
__device__ __half g_hh [(size_t)B_ * L_ * D_];         // modulated hidden (fp16)
__device__ __half g_wqh[(size_t)3 * D_ * D_];          // w_qkv fp16
__device__ __half g_woh[(size_t)D_ * D_];              // w_out fp16
__device__ __half g_qh [(size_t)B_ * NH_ * L_ * HD_];  // q (pre-scaled), fp16
__device__ __half g_kh [(size_t)B_ * NH_ * L_ * HD_];
__device__ __half g_vh [(size_t)B_ * NH_ * L_ * HD_];
__device__ __half g_oh [(size_t)B_ * L_ * D_];         // attn out fp16

// ---------------- helpers ------------------------------------------------
__device__ __forceinline__ uint32_t pack_h2(float lo, float hi) {
    uint32_t u;
    asm("cvt.rn.f16x2.f32 %0, %1, %2;" : "=r"(u) : "f"(hi), "f"(lo));
    return u;
}
__device__ __forceinline__ float2 unpack_h2(uint32_t u) {
    __half2 h = *reinterpret_cast<__half2*>(&u);
    return __half22float2(h);
}
__device__ __forceinline__ void mma_f16(float* c, const uint32_t* a,
                                        const uint32_t* b) {
    asm volatile(
        "mma.sync.aligned.m16n8k16.row.col.f32.f16.f16.f32 "
        "{%0,%1,%2,%3}, {%4,%5,%6,%7}, {%8,%9}, {%0,%1,%2,%3};"
        : "+f"(c[0]), "+f"(c[1]), "+f"(c[2]), "+f"(c[3])
        : "r"(a[0]), "r"(a[1]), "r"(a[2]), "r"(a[3]), "r"(b[0]), "r"(b[1]));
}
#define LDSM_X4(r0, r1, r2, r3, addr)                                         \
    asm volatile("ldmatrix.sync.aligned.m8n8.x4.shared.b16 {%0,%1,%2,%3}, [%4];" \
        : "=r"(r0), "=r"(r1), "=r"(r2), "=r"(r3) : "r"(addr))
#define LDSM_X4_T(r0, r1, r2, r3, addr)                                       \
    asm volatile("ldmatrix.sync.aligned.m8n8.x4.trans.shared.b16 {%0,%1,%2,%3}, [%4];" \
        : "=r"(r0), "=r"(r1), "=r"(r2), "=r"(r3) : "r"(addr))

// ---------------- one-shot weight conversion to fp16 ---------------------
__global__ void cvtw_h(__half* __restrict__ dst, const float* __restrict__ src) {
    int i = (blockIdx.x * 256 + threadIdx.x) * 4;
    float4 v = *reinterpret_cast<const float4*>(src + i);
    uint2 u = make_uint2(pack_h2(v.x, v.y), pack_h2(v.z, v.w));
    *reinterpret_cast<uint2*>(dst + i) = u;
}

// ======= fp16 ldmatrix GEMM NT: C[M,N] = A[M,K]*B[N,K]^T =================
// BM=BN=128, BK=32, 4-stage cp.async ring (64KB dynamic), 256 threads,
// warp tile 64x32, 2 CTAs/SM. wait_group 2 => two stage-groups in flight.
template <bool HALF_OUT>
__global__ void __launch_bounds__(256, 2)
gemm_h(void* __restrict__ Cv, const __half* __restrict__ A,
       const __half* __restrict__ B, int M, int N, int K) {
    extern __shared__ uint32_t dsm[];
    uint32_t sA = (uint32_t)__cvta_generic_to_shared(dsm);
    uint32_t sB = sA + 4 * 8192;

    int tid = threadIdx.x;
    int m0 = blockIdx.y * 128, n0 = blockIdx.x * 128;
    int wid = tid >> 5, lane = tid & 31;
    int wm = (wid & 1) * 64, wn = (wid >> 1) * 32;
    int qr = lane >> 2, qc = lane & 3;
    int i8 = lane & 7, g = lane >> 3;

    int cr = tid >> 2, cc = tid & 3;
    int cw  = 4 * (cc ^ ((cr >> 1) & 3));
    int cw2 = 4 * (cc ^ (((cr + 64) >> 1) & 3));
    const __half* Asrc0 = A + (size_t)(m0 + cr) * K + cc * 8;
    const __half* Asrc1 = A + (size_t)(m0 + cr + 64) * K + cc * 8;
    const __half* Bsrc0 = B + (size_t)(n0 + cr) * K + cc * 8;
    const __half* Bsrc1 = B + (size_t)(n0 + cr + 64) * K + cc * 8;

#define COPY_STAGE(s, kh)                                                     \
    do {                                                                      \
        uint32_t o1 = (s) * 8192 + (cr * 16) * 4;                             \
        uint32_t o2 = (s) * 8192 + ((cr + 64) * 16) * 4;                      \
        asm volatile("cp.async.cg.shared.global [%0], [%1], 16;"              \
                     :: "r"(sA + o1 + cw * 4), "l"(Asrc0 + (kh)) : "memory"); \
        asm volatile("cp.async.cg.shared.global [%0], [%1], 16;"              \
                     :: "r"(sA + o2 + cw2 * 4), "l"(Asrc1 + (kh)) : "memory");\
        asm volatile("cp.async.cg.shared.global [%0], [%1], 16;"              \
                     :: "r"(sB + o1 + cw * 4), "l"(Bsrc0 + (kh)) : "memory"); \
        asm volatile("cp.async.cg.shared.global [%0], [%1], 16;"              \
                     :: "r"(sB + o2 + cw2 * 4), "l"(Bsrc1 + (kh)) : "memory");\
    } while (0)
#define CP_COMMIT() asm volatile("cp.async.commit_group;" ::: "memory")

    COPY_STAGE(0, 0);  CP_COMMIT();
    COPY_STAGE(1, 32); CP_COMMIT();
    COPY_STAGE(2, 64); CP_COMMIT();

    int arow = wm + i8 + (g & 1) * 8;
    int acg  = g >> 1;
    int brow = wn + i8 + (g >> 1) * 8;
    int bcg  = g & 1;

    float acc[4][4][4] = {};
    int NT = K >> 5;
    for (int kt = 0; kt < NT; kt++) {
        int s = kt & 3;
        asm volatile("cp.async.wait_group 2;" ::: "memory");
        __syncthreads();
        int kp = kt + 3;
        if (kp < NT) COPY_STAGE(kp & 3, kp * 32);
        CP_COMMIT();

        uint32_t stoff = s * 8192;
#pragma unroll
        for (int kc = 0; kc < 2; kc++) {
            uint32_t af[4][4], bf[4][2];
#pragma unroll
            for (int mt = 0; mt < 4; mt++) {
                int r = arow + mt * 16;
                int w = r * 16 + 4 * ((2 * kc + acg) ^ ((r >> 1) & 3));
                LDSM_X4(af[mt][0], af[mt][1], af[mt][2], af[mt][3],
                        sA + stoff + w * 4);
            }
#pragma unroll
            for (int nt2 = 0; nt2 < 2; nt2++) {
                int r = brow + nt2 * 16;
                int w = r * 16 + 4 * ((2 * kc + bcg) ^ ((r >> 1) & 3));
                LDSM_X4(bf[nt2 * 2][0], bf[nt2 * 2][1],
                        bf[nt2 * 2 + 1][0], bf[nt2 * 2 + 1][1],
                        sB + stoff + w * 4);
            }
#pragma unroll
            for (int mt = 0; mt < 4; mt++)
#pragma unroll
                for (int nt = 0; nt < 4; nt++)
                    mma_f16(acc[mt][nt], af[mt], bf[nt]);
        }
    }

#pragma unroll
    for (int mt = 0; mt < 4; mt++) {
        int row = m0 + wm + mt * 16 + qr;
#pragma unroll
        for (int nt = 0; nt < 4; nt++) {
            int col = n0 + wn + nt * 8 + qc * 2;
            if (HALF_OUT) {
                __half* C = (__half*)Cv;
                *reinterpret_cast<uint32_t*>(C + (size_t)row * N + col) =
                    pack_h2(acc[mt][nt][0], acc[mt][nt][1]);
                *reinterpret_cast<uint32_t*>(C + (size_t)(row + 8) * N + col) =
                    pack_h2(acc[mt][nt][2], acc[mt][nt][3]);
            } else {
                float* C = (float*)Cv;
                *reinterpret_cast<float2*>(C + (size_t)row * N + col) =
                    make_float2(acc[mt][nt][0], acc[mt][nt][1]);
                *reinterpret_cast<float2*>(C + (size_t)(row + 8) * N + col) =
                    make_float2(acc[mt][nt][2], acc[mt][nt][3]);
            }
        }
    }
#undef COPY_STAGE
#undef CP_COMMIT
}

// ---------------- 1) ss = condition @ w_ada^T  (warp per output) ---------
__global__ void ada_kernel(const float* __restrict__ cond,
                           const float* __restrict__ w_ada) {
    int w    = (blockIdx.x * blockDim.x + threadIdx.x) >> 5;
    int lane = threadIdx.x & 31;
    int b = w >> 12;
    int j = w & 4095;
    const float4* c4 = reinterpret_cast<const float4*>(cond + (size_t)b * DC_);
    const float4* w4 = reinterpret_cast<const float4*>(w_ada + (size_t)j * DC_);
    float s = 0.f;
#pragma unroll
    for (int q = 0; q < 16; q++) {
        float4 a  = c4[lane + q * 32];
        float4 bb = w4[lane + q * 32];
        s += a.x * bb.x + a.y * bb.y + a.z * bb.z + a.w * bb.w;
    }
#pragma unroll
    for (int o = 16; o; o >>= 1) s += __shfl_xor_sync(0xffffffffu, s, o);
    if (lane == 0) g_ss[b * 4096 + j] = s;
}

// ------- 2) h = fp16(rmsnorm(x)*(1+scale)+shift) -------------------------
__global__ void rmsada_kernel(const float* __restrict__ x) {
    int row = blockIdx.x;
    int b   = row >> 11;
    int t   = threadIdx.x;
    const float4* xr = reinterpret_cast<const float4*>(x + (size_t)row * D_);
    float4 v0 = xr[t], v1 = xr[t + 256];
    float s = v0.x*v0.x + v0.y*v0.y + v0.z*v0.z + v0.w*v0.w
            + v1.x*v1.x + v1.y*v1.y + v1.z*v1.z + v1.w*v1.w;
    __shared__ float red[256];
    red[t] = s; __syncthreads();
    for (int o = 128; o; o >>= 1) { if (t < o) red[t] += red[t + o]; __syncthreads(); }
    float inv = rsqrtf(red[0] * (1.0f / D_) + EPS);
    const float* shift = g_ss + b * 4096;
    const float* scale = shift + D_;
    uint2* hr = reinterpret_cast<uint2*>(g_hh + (size_t)row * D_);
    {
        int d = t * 4;
        float4 sc = *reinterpret_cast<const float4*>(scale + d);
        float4 sh = *reinterpret_cast<const float4*>(shift + d);
        hr[t] = make_uint2(
            pack_h2(v0.x * inv * (1.f + sc.x) + sh.x,
                    v0.y * inv * (1.f + sc.y) + sh.y),
            pack_h2(v0.z * inv * (1.f + sc.z) + sh.z,
                    v0.w * inv * (1.f + sc.w) + sh.w));
    }
    {
        int d = (t + 256) * 4;
        float4 sc = *reinterpret_cast<const float4*>(scale + d);
        float4 sh = *reinterpret_cast<const float4*>(shift + d);
        hr[t + 256] = make_uint2(
            pack_h2(v1.x * inv * (1.f + sc.x) + sh.x,
                    v1.y * inv * (1.f + sc.y) + sh.y),
            pack_h2(v1.z * inv * (1.f + sc.z) + sh.z,
                    v1.w * inv * (1.f + sc.w) + sh.w));
    }
}

// ------- 4) per-head rmsnorm + qk_w + RoPE -> fp16 q/k/v -----------------
__global__ void qkrope_kernel(const float* __restrict__ rope,
                              const float* __restrict__ qkw) {
    int row = blockIdx.x;                // b*L + l
    int b   = row >> 11;
    int l   = row & 2047;
    int t   = threadIdx.x;
    int h   = t >> 3;
    int sub = t & 7;
    int d0  = sub * 8;

    const __half* src = g_qkvh + (size_t)row * (3 * D_) + h * HD_ + d0;
    uint4 qu = *reinterpret_cast<const uint4*>(src);
    uint4 ku = *reinterpret_cast<const uint4*>(src + D_);
    uint4 vu = *reinterpret_cast<const uint4*>(src + 2 * D_);

    float2 qf[4], kf[4];
    qf[0] = unpack_h2(qu.x); qf[1] = unpack_h2(qu.y);
    qf[2] = unpack_h2(qu.z); qf[3] = unpack_h2(qu.w);
    kf[0] = unpack_h2(ku.x); kf[1] = unpack_h2(ku.y);
    kf[2] = unpack_h2(ku.z); kf[3] = unpack_h2(ku.w);

    float sq = 0.f, sk = 0.f;
#pragma unroll
    for (int i = 0; i < 4; i++) {
        sq += qf[i].x * qf[i].x + qf[i].y * qf[i].y;
        sk += kf[i].x * kf[i].x + kf[i].y * kf[i].y;
    }
#pragma unroll
    for (int o = 4; o; o >>= 1) {
        sq += __shfl_xor_sync(0xffffffffu, sq, o);
        sk += __shfl_xor_sync(0xffffffffu, sk, o);
    }
    float qi = rsqrtf(sq * (1.0f / HD_) + EPS);
    float ki = rsqrtf(sk * (1.0f / HD_) + EPS);

    const float4* w4 = reinterpret_cast<const float4*>(qkw + d0);
    float4 w0 = w4[0], w1 = w4[1];
    const float* rbase = rope + (size_t)l * HD_ + d0;
    float4 r00 = *reinterpret_cast<const float4*>(rbase);
    float4 r01 = *reinterpret_cast<const float4*>(rbase + 4);
    float4 r10 = *reinterpret_cast<const float4*>(rbase + (size_t)L_ * HD_);
    float4 r11 = *reinterpret_cast<const float4*>(rbase + (size_t)L_ * HD_ + 4);

    float w[8]  = {w0.x, w0.y, w0.z, w0.w, w1.x, w1.y, w1.z, w1.w};
    float r0[8] = {r00.x, r00.y, r00.z, r00.w, r01.x, r01.y, r01.z, r01.w};
    float r1[8] = {r10.x, r10.y, r10.z, r10.w, r11.x, r11.y, r11.z, r11.w};

    uint32_t qo[4], ko[4];
#pragma unroll
    for (int i = 0; i < 4; i++) {
        float q0 = qf[i].x * qi * w[2 * i];
        float q1 = qf[i].y * qi * w[2 * i + 1];
        float k0 = kf[i].x * ki * w[2 * i];
        float k1 = kf[i].y * ki * w[2 * i + 1];
        float qx = q0 * r0[2 * i]     - q1 * r1[2 * i];
        float qy = q1 * r0[2 * i + 1] + q0 * r1[2 * i + 1];
        float kx = k0 * r0[2 * i]     - k1 * r1[2 * i];
        float ky = k1 * r0[2 * i + 1] + k0 * r1[2 * i + 1];
        qo[i] = pack_h2(qx * 0.125f, qy * 0.125f);
        ko[i] = pack_h2(kx, ky);
    }

    size_t orow = ((size_t)(b * NH_ + h) * L_ + l) * HD_ + d0;
    *reinterpret_cast<uint4*>(g_qh + orow) = make_uint4(qo[0], qo[1], qo[2], qo[3]);
    *reinterpret_cast<uint4*>(g_kh + orow) = make_uint4(ko[0], ko[1], ko[2], ko[3]);
    *reinterpret_cast<uint4*>(g_vh + orow) = vu;
}

// ============ 5) fp16 flash attention: BQ=128, register P ================
__global__ void __launch_bounds__(256, 2) attn_h() {
    __shared__ uint32_t Qs[128][32];
    __shared__ uint32_t Ks[2][32][32];
    __shared__ uint32_t Vs[2][32][32];

    int tid  = threadIdx.x;
    int wid  = tid >> 5, lane = tid & 31;
    int qr   = lane >> 2, qc = lane & 3;
    int i8   = lane & 7, g = lane >> 3;
    int bh   = blockIdx.y;
    int bq0  = blockIdx.x * 128;
    int qrow = wid * 16;

    const __half* Qg = g_qh + (size_t)bh * L_ * HD_;
    const __half* Kg = g_kh + (size_t)bh * L_ * HD_;
    const __half* Vg = g_vh + (size_t)bh * L_ * HD_;

    int pr = tid >> 3, pch = tid & 7;
    int pw = (pch * 4) ^ ((pr & 7) << 2);
    uint4 kp = *reinterpret_cast<const uint4*>(Kg + (size_t)pr * HD_ + pch * 8);
    uint4 vp = *reinterpret_cast<const uint4*>(Vg + (size_t)pr * HD_ + pch * 8);

#pragma unroll
    for (int t = 0; t < 4; t++) {
        int idx = tid + t * 256;
        int r = idx >> 3, ch = idx & 7;
        uint4 u = *reinterpret_cast<const uint4*>(Qg + (size_t)(bq0 + r) * HD_ + ch * 8);
        *reinterpret_cast<uint4*>(&Qs[r][(ch * 4) ^ ((r & 7) << 2)]) = u;
    }
    __syncthreads();

    uint32_t aq[4][4];
    uint32_t qbase = (uint32_t)__cvta_generic_to_shared(&Qs[0][0]);
    {
        int r = qrow + i8 + (g & 1) * 8;
#pragma unroll
        for (int kk = 0; kk < 4; kk++) {
            int ch = 2 * kk + (g >> 1);
            int w = r * 32 + ((ch * 4) ^ ((r & 7) << 2));
            LDSM_X4(aq[kk][0], aq[kk][1], aq[kk][2], aq[kk][3], qbase + w * 4);
        }
    }

    {
        *reinterpret_cast<uint4*>(&Ks[0][pr][pw]) = kp;
        *reinterpret_cast<uint4*>(&Vs[0][pr][pw]) = vp;
    }
    __syncthreads();

    uint32_t kbase = (uint32_t)__cvta_generic_to_shared(&Ks[0][0][0]);
    uint32_t vbase = (uint32_t)__cvta_generic_to_shared(&Vs[0][0][0]);
    int krow = i8 + (g >> 1) * 8;
    int vrow = i8 + (g & 1) * 8;
    int vcg  = g >> 1;

    float o[8][4] = {};
    float m_lo = -INFINITY, m_hi = -INFINITY, l_lo = 0.f, l_hi = 0.f;
    int p = 0;

    for (int c = 0; c < 64; c++) {
        if (c < 63) {
            size_t koff = (size_t)(c + 1) * 32;
            kp = *reinterpret_cast<const uint4*>(Kg + (koff + pr) * HD_ + pch * 8);
            vp = *reinterpret_cast<const uint4*>(Vg + (koff + pr) * HD_ + pch * 8);
        }

        float s[4][4] = {};
        uint32_t pbase = kbase + p * 4096;
#pragma unroll
        for (int kk = 0; kk < 4; kk++) {
            uint32_t b0[4], b1[4];
            {
                int r = krow;
                int ch = 2 * kk + (g & 1);
                int w = r * 32 + ((ch * 4) ^ ((r & 7) << 2));
                LDSM_X4(b0[0], b0[1], b0[2], b0[3], pbase + w * 4);
            }
            {
                int r = krow + 16;
                int ch = 2 * kk + (g & 1);
                int w = r * 32 + ((ch * 4) ^ ((r & 7) << 2));
                LDSM_X4(b1[0], b1[1], b1[2], b1[3], pbase + w * 4);
            }
            mma_f16(s[0], aq[kk], b0);
            mma_f16(s[1], aq[kk], b0 + 2);
            mma_f16(s[2], aq[kk], b1);
            mma_f16(s[3], aq[kk], b1 + 2);
        }

        float mx_lo = -INFINITY, mx_hi = -INFINITY;
#pragma unroll
        for (int j = 0; j < 4; j++) {
            mx_lo = fmaxf(mx_lo, fmaxf(s[j][0], s[j][1]));
            mx_hi = fmaxf(mx_hi, fmaxf(s[j][2], s[j][3]));
        }
        mx_lo = fmaxf(mx_lo, __shfl_xor_sync(0xffffffffu, mx_lo, 1));
        mx_lo = fmaxf(mx_lo, __shfl_xor_sync(0xffffffffu, mx_lo, 2));
        mx_hi = fmaxf(mx_hi, __shfl_xor_sync(0xffffffffu, mx_hi, 1));
        mx_hi = fmaxf(mx_hi, __shfl_xor_sync(0xffffffffu, mx_hi, 2));

        float mn_lo = fmaxf(m_lo, mx_lo);
        float mn_hi = fmaxf(m_hi, mx_hi);
        float cf_lo = __expf(m_lo - mn_lo);
        float cf_hi = __expf(m_hi - mn_hi);
        m_lo = mn_lo; m_hi = mn_hi;

        uint32_t ap[2][4];
        float ls_lo = 0.f, ls_hi = 0.f;
#pragma unroll
        for (int kk2 = 0; kk2 < 2; kk2++) {
#pragma unroll
            for (int jj = 0; jj < 2; jj++) {
                int j = 2 * kk2 + jj;
                uint32_t plo = pack_h2(__expf(s[j][0] - mn_lo),
                                       __expf(s[j][1] - mn_lo));
                uint32_t phi = pack_h2(__expf(s[j][2] - mn_hi),
                                       __expf(s[j][3] - mn_hi));
                ap[kk2][2 * jj]     = plo;
                ap[kk2][2 * jj + 1] = phi;
                float2 flo = unpack_h2(plo), fhi = unpack_h2(phi);
                ls_lo += flo.x + flo.y;
                ls_hi += fhi.x + fhi.y;
            }
        }
        ls_lo += __shfl_xor_sync(0xffffffffu, ls_lo, 1);
        ls_lo += __shfl_xor_sync(0xffffffffu, ls_lo, 2);
        ls_hi += __shfl_xor_sync(0xffffffffu, ls_hi, 1);
        ls_hi += __shfl_xor_sync(0xffffffffu, ls_hi, 2);
        l_lo = l_lo * cf_lo + ls_lo;
        l_hi = l_hi * cf_hi + ls_hi;

#pragma unroll
        for (int n = 0; n < 8; n++) {
            o[n][0] *= cf_lo; o[n][1] *= cf_lo;
            o[n][2] *= cf_hi; o[n][3] *= cf_hi;
        }

        uint32_t vpb = vbase + p * 4096;
#pragma unroll
        for (int kk2 = 0; kk2 < 2; kk2++) {
            int r = kk2 * 16 + vrow;
#pragma unroll
            for (int np = 0; np < 4; np++) {
                int ch = 2 * np + vcg;
                int w = r * 32 + ((ch * 4) ^ ((r & 7) << 2));
                uint32_t bv0[2], bv1[2];
                LDSM_X4_T(bv0[0], bv0[1], bv1[0], bv1[1], vpb + w * 4);
                mma_f16(o[2 * np],     ap[kk2], bv0);
                mma_f16(o[2 * np + 1], ap[kk2], bv1);
            }
        }

        if (c < 63) {
            int np2 = p ^ 1;
            *reinterpret_cast<uint4*>(&Ks[np2][pr][pw]) = kp;
            *reinterpret_cast<uint4*>(&Vs[np2][pr][pw]) = vp;
            __syncthreads();
            p = np2;
        }
    }

    int b = bh >> 5, h = bh & 31;
    float inv_lo = 1.f / l_lo, inv_hi = 1.f / l_hi;
    __half* base_lo = g_oh + (size_t)(b * L_ + bq0 + qrow + qr) * D_ + h * HD_;
    __half* base_hi = g_oh + (size_t)(b * L_ + bq0 + qrow + qr + 8) * D_ + h * HD_;
#pragma unroll
    for (int n = 0; n < 8; n++) {
        *reinterpret_cast<uint32_t*>(base_lo + 8 * n + 2 * qc) =
            pack_h2(o[n][0] * inv_lo, o[n][1] * inv_lo);
        *reinterpret_cast<uint32_t*>(base_hi + 8 * n + 2 * qc) =
            pack_h2(o[n][2] * inv_hi, o[n][3] * inv_hi);
    }
}

// -------------------------------------------------------------------------
#define GEMM_SMEM (8 * 8192)           // 64 KB: 4 stages x (8KB A + 8KB B)

extern "C" void kernel_launch(void* const* d_in, const int* in_sizes, int n_in,
                              void* d_out, int out_size) {
    const float* x     = (const float*)d_in[0];
    const float* cond  = (const float*)d_in[1];
    const float* rope  = (const float*)d_in[2];
    const float* w_ada = (const float*)d_in[3];
    const float* w_qkv = (const float*)d_in[4];
    const float* w_out = (const float*)d_in[5];
    const float* qk_w  = (const float*)d_in[6];
    float* out = (float*)d_out;

    void* p;
    cudaGetSymbolAddress(&p, g_qkvh); __half* pqkv = (__half*)p;
    cudaGetSymbolAddress(&p, g_hh);   __half* phh  = (__half*)p;
    cudaGetSymbolAddress(&p, g_wqh);  __half* pwq  = (__half*)p;
    cudaGetSymbolAddress(&p, g_woh);  __half* pwo  = (__half*)p;
    cudaGetSymbolAddress(&p, g_oh);   __half* poh  = (__half*)p;

    cudaFuncSetAttribute(gemm_h<true>,
                         cudaFuncAttributeMaxDynamicSharedMemorySize, GEMM_SMEM);
    cudaFuncSetAttribute(gemm_h<false>,
                         cudaFuncAttributeMaxDynamicSharedMemorySize, GEMM_SMEM);

    cvtw_h<<<3 * D_ * D_ / 1024, 256>>>(pwq, w_qkv);
    cvtw_h<<<D_ * D_ / 1024, 256>>>(pwo, w_out);
    ada_kernel<<<1024, 256>>>(cond, w_ada);
    rmsada_kernel<<<B_ * L_, 256>>>(x);
    gemm_h<true><<<dim3(3 * D_ / 128, B_ * L_ / 128), 256, GEMM_SMEM>>>(
        pqkv, phh, pwq, B_ * L_, 3 * D_, D_);
    qkrope_kernel<<<B_ * L_, 256>>>(rope, qk_w);
    attn_h<<<dim3(L_ / 128, B_ * NH_), 256>>>();
    gemm_h<false><<<dim3(D_ / 128, B_ * L_ / 128), 256, GEMM_SMEM>>>(
        out, poh, pwo, B_ * L_, D_, D_);
}